// round 1
// baseline (speedup 1.0000x reference)
#include <cuda_runtime.h>
#include <math.h>

#define BB   8
#define PP   4096
#define NN   (BB*PP)
#define KK   20
#define LL   10
#define FF   32
#define KSS  5
#define NCLS 40
#define R24  24   // N*3/P rows after reshape

// -------- persistent scratch (static device globals; no runtime allocation) ----
__device__ float g_node[NN*FF];     // 4 MB
__device__ float g_v3[NN*3];
__device__ float g_stats[2*FF];     // [0..31] mu, [32..63] inv_std
__device__ float g_ys[R24*FF];

// ---------------- power iteration (matches jax reference exactly) --------------
__device__ __forceinline__ void power_iter(
    float m00, float m01, float m02, float m11, float m12, float m22,
    float &vx, float &vy, float &vz, float &lam)
{
    float x = 0.57735026918962576f, y = x, z = x;
    #pragma unroll
    for (int it = 0; it < 5; ++it) {
        float wx = m00*x + m01*y + m02*z;
        float wy = m01*x + m11*y + m12*z;
        float wz = m02*x + m12*y + m22*z;
        float nr = sqrtf(wx*wx + wy*wy + wz*wz);
        float inv = 1.0f / (nr + 1e-12f);
        x = wx*inv; y = wy*inv; z = wz*inv;
    }
    float wx = m00*x + m01*y + m02*z;
    float wy = m01*x + m11*y + m12*z;
    float wz = m02*x + m12*y + m22*z;
    lam = x*wx + y*wy + z*wz;
    vx = x; vy = y; vz = z;
}

// ---------------- kernel 1: fused KNN + eig + spline conv ---------------------
// grid: 256 blocks (8 batches x 32 chunks), 128 threads, 1 query point / thread
// dyn smem: 4096 float4 positions (64KB) + Wsp transposed float2 [16][128] (16KB)
__global__ void __launch_bounds__(128, 2) k_point(
    const float* __restrict__ pos,
    const float* __restrict__ Wsp,
    const float* __restrict__ root,
    const float* __restrict__ bias)
{
    extern __shared__ float smem_raw[];
    float4* sp = (float4*)smem_raw;                 // [4096]
    float2* sw = (float2*)(smem_raw + 4*PP);        // [16*128]

    int b     = blockIdx.x >> 5;
    int chunk = blockIdx.x & 31;
    int tid   = threadIdx.x;

    // cooperative loads
    for (int i = tid; i < PP; i += 128) {
        const float* p = pos + (size_t)(b*PP + i)*3;
        sp[i] = make_float4(p[0], p[1], p[2], 0.f);
    }
    for (int i = tid; i < 16*125; i += 128) {
        int f2 = i / 125, r = i - f2*125;
        sw[f2*128 + r] = make_float2(Wsp[r*32 + 2*f2], Wsp[r*32 + 2*f2 + 1]);
    }
    __syncthreads();

    int self = chunk*128 + tid;
    int n    = b*PP + self;
    float qx = sp[self].x, qy = sp[self].y, qz = sp[self].z;

    // ---- brute-force top-K (sorted ascending; ties keep lower index) ----
    float dist[KK]; int idx[KK];
    #pragma unroll
    for (int s = 0; s < KK; ++s) { dist[s] = 3.4e38f; idx[s] = 0; }

    #pragma unroll 4
    for (int j = 0; j < PP; ++j) {
        float4 c = sp[j];
        float dx = c.x - qx, dy = c.y - qy, dz = c.z - qz;
        float d  = fmaf(dz, dz, fmaf(dy, dy, dx*dx));
        if (d < dist[KK-1]) {
            if (j != self) {
                dist[KK-1] = d; idx[KK-1] = j;
                #pragma unroll
                for (int s = KK-1; s > 0; --s) {
                    if (dist[s] < dist[s-1]) {
                        float td = dist[s]; dist[s] = dist[s-1]; dist[s-1] = td;
                        int   ti = idx[s];  idx[s]  = idx[s-1];  idx[s-1]  = ti;
                    }
                }
            }
        }
    }

    // ---- covariance over the L nearest ----
    float cxx=0,cxy=0,cxz=0,cyy=0,cyz=0,czz=0;
    #pragma unroll
    for (int l = 0; l < LL; ++l) {
        float4 c = sp[idx[l]];
        float dx = c.x - qx, dy = c.y - qy, dz = c.z - qz;
        cxx += dx*dx; cxy += dx*dy; cxz += dx*dz;
        cyy += dy*dy; cyz += dy*dz; czz += dz*dz;
    }

    // ---- eigenvectors: power iteration + deflation + cross ----
    float v1x,v1y,v1z,l1;
    power_iter(cxx,cxy,cxz,cyy,cyz,czz, v1x,v1y,v1z,l1);
    float m00 = cxx - l1*v1x*v1x, m01 = cxy - l1*v1x*v1y, m02 = cxz - l1*v1x*v1z;
    float m11 = cyy - l1*v1y*v1y, m12 = cyz - l1*v1y*v1z, m22 = czz - l1*v1z*v1z;
    float v2x,v2y,v2z,l2;
    power_iter(m00,m01,m02,m11,m12,m22, v2x,v2y,v2z,l2);
    float v3x = v1y*v2z - v1z*v2y;
    float v3y = v1z*v2x - v1x*v2z;
    float v3z = v1x*v2y - v1y*v2x;
    float n3  = sqrtf(v3x*v3x + v3y*v3y + v3z*v3z);
    float i3  = 1.0f / (n3 + 1e-12f);
    v3x *= i3; v3y *= i3; v3z *= i3;

    // ---- pass A: sum of dirc[:,2], max|dirc| components ----
    float ssum = 0.f, mx12 = 0.f, mx3 = 0.f;
    #pragma unroll
    for (int k = 0; k < KK; ++k) {
        float4 c = sp[idx[k]];
        float dx = c.x - qx, dy = c.y - qy, dz = c.z - qz;
        float d1 = dx*v1x + dy*v1y + dz*v1z;
        float d2 = dx*v2x + dy*v2y + dz*v2z;
        float d3 = dx*v3x + dy*v3y + dz*v3z;
        ssum += d3;
        mx12 = fmaxf(mx12, fmaxf(fabsf(d1), fabsf(d2)));
        mx3  = fmaxf(mx3, fabsf(d3));
    }
    float sgn    = (ssum > 0.f) ? 1.f : ((ssum < 0.f) ? -1.f : 0.f);
    float maxabs = (sgn != 0.f) ? fmaxf(mx12, mx3) : mx12;
    float rm     = 1.0f / maxabs;

    // ---- pass B: spline conv (trilinear basis on 5^3 grid), F=32 ----
    float msg[FF];
    #pragma unroll
    for (int f = 0; f < FF; ++f) msg[f] = 0.f;

    for (int k = 0; k < KK; ++k) {
        float4 c = sp[idx[k]];
        float dx = c.x - qx, dy = c.y - qy, dz = c.z - qz;
        float d0 = dx*v1x + dy*v1y + dz*v1z;
        float d1 = dx*v2x + dy*v2y + dz*v2z;
        float d2 = (dx*v3x + dy*v3y + dz*v3z) * sgn;

        float u0 = d0*rm*0.5f + 0.5f;
        float u1 = d1*rm*0.5f + 0.5f;
        float u2 = d2*rm*0.5f + 0.5f;
        float vv0 = u0*4.f, vv1 = u1*4.f, vv2 = u2*4.f;
        float fl0 = floorf(vv0), fl1 = floorf(vv1), fl2 = floorf(vv2);
        float fr0 = vv0 - fl0,  fr1 = vv1 - fl1,  fr2 = vv2 - fl2;
        int i0 = (int)fl0, i1 = (int)fl1, i2 = (int)fl2;

        int ia0 = min(max(i0,   0), 4), ib0 = min(max(i0+1, 0), 4);
        int ia1 = min(max(i1,   0), 4), ib1 = min(max(i1+1, 0), 4);
        int ia2 = min(max(i2,   0), 4), ib2 = min(max(i2+1, 0), 4);
        float wa0 = 1.f - fr0, wb0 = fr0;
        float wa1 = 1.f - fr1, wb1 = fr1;
        float wa2 = 1.f - fr2, wb2 = fr2;

        #pragma unroll
        for (int s = 0; s < 8; ++s) {
            int bit0 = (s >> 2) & 1, bit1 = (s >> 1) & 1, bit2 = s & 1;
            float bas = (bit0 ? wb0 : wa0) * (bit1 ? wb1 : wa1) * (bit2 ? wb2 : wa2);
            int j0 = bit0 ? ib0 : ia0;
            int j1 = bit1 ? ib1 : ia1;
            int j2 = bit2 ? ib2 : ia2;
            int flat = (j0*KSS + j1)*KSS + j2;
            #pragma unroll
            for (int f2 = 0; f2 < 16; ++f2) {
                float2 w = sw[f2*128 + flat];
                msg[2*f2]   += bas * w.x;
                msg[2*f2+1] += bas * w.y;
            }
        }
    }

    #pragma unroll
    for (int f = 0; f < FF; ++f)
        g_node[(size_t)n*FF + f] = msg[f] * (1.0f/(float)KK) + root[f] + bias[f];
    g_v3[n*3+0] = v3x; g_v3[n*3+1] = v3y; g_v3[n*3+2] = v3z;
}

// ---------------- kernel 2: per-channel batch stats ----------------------------
__global__ void k_stats()
{
    int c = blockIdx.x;
    int tid = threadIdx.x;
    double s = 0.0, s2 = 0.0;
    for (int i = tid; i < NN; i += 256) {
        float x = g_node[(size_t)i*FF + c];
        s  += (double)x;
        s2 += (double)x * (double)x;
    }
    __shared__ double rs[256], rs2[256];
    rs[tid] = s; rs2[tid] = s2;
    __syncthreads();
    for (int off = 128; off; off >>= 1) {
        if (tid < off) { rs[tid] += rs[tid+off]; rs2[tid] += rs2[tid+off]; }
        __syncthreads();
    }
    if (tid == 0) {
        double mu  = rs[0] / (double)NN;
        double var = rs2[0] / (double)NN - mu*mu;
        g_stats[c]      = (float)mu;
        g_stats[FF + c] = (float)(1.0 / sqrt(var + 1e-5));
    }
}

// ---------------- kernel 3: sigmoid + reshape(-1,P,F).mean(1) ------------------
// grid 768 = 24 rows x 32 cols, 128 threads
__global__ void k_ys(const float* __restrict__ gamma, const float* __restrict__ beta)
{
    int r = blockIdx.x >> 5;
    int j = blockIdx.x & 31;
    int tid = threadIdx.x;
    float sum = 0.f;
    for (int p = tid; p < PP; p += 128) {
        int flat = r*(PP*FF) + p*FF + j;
        int nn   = flat / 96;
        int rem  = flat - nn*96;
        int fch  = rem / 3;
        int c    = rem - fch*3;
        float x  = g_node[(size_t)nn*FF + fch];
        float xb = gamma[fch] * (x - g_stats[fch]) * g_stats[FF + fch] + beta[fch];
        float o  = xb * g_v3[nn*3 + c];
        sum += 1.0f / (1.0f + expf(-o));
    }
    __shared__ float red[128];
    red[tid] = sum;
    __syncthreads();
    for (int off = 64; off; off >>= 1) {
        if (tid < off) red[tid] += red[tid+off];
        __syncthreads();
    }
    if (tid == 0) g_ys[r*FF + j] = red[0] / (float)PP;
}

// ---------------- kernel 4: MLP head + log_softmax -----------------------------
__global__ void k_head(
    const float* __restrict__ W1, const float* __restrict__ b1,
    const float* __restrict__ W2, const float* __restrict__ b2,
    float* __restrict__ out)
{
    __shared__ float ys[R24*FF];
    __shared__ float y1[R24*256];
    __shared__ float zz[R24*NCLS];
    int tid = threadIdx.x;   // 256

    for (int i = tid; i < R24*FF; i += 256) ys[i] = g_ys[i];
    __syncthreads();

    // y1[r][h], h = tid
    {
        float bh = b1[tid];
        for (int r = 0; r < R24; ++r) {
            float acc = bh;
            #pragma unroll
            for (int f = 0; f < FF; ++f) acc += ys[r*FF + f] * W1[f*256 + tid];
            y1[r*256 + tid] = acc > 0.f ? acc : expm1f(acc);
        }
    }
    __syncthreads();

    for (int i = tid; i < R24*NCLS; i += 256) {
        int r = i / NCLS, c = i - r*NCLS;
        float acc = b2[c];
        for (int h = 0; h < 256; ++h) acc += y1[r*256 + h] * W2[h*NCLS + c];
        zz[i] = acc;
    }
    __syncthreads();

    if (tid < R24) {
        int r = tid;
        float mx = -3.4e38f;
        for (int c = 0; c < NCLS; ++c) mx = fmaxf(mx, zz[r*NCLS + c]);
        float se = 0.f;
        for (int c = 0; c < NCLS; ++c) se += expf(zz[r*NCLS + c] - mx);
        float lse = mx + logf(se);
        for (int c = 0; c < NCLS; ++c) out[r*NCLS + c] = zz[r*NCLS + c] - lse;
    }
}

// ---------------- launch --------------------------------------------------------
extern "C" void kernel_launch(void* const* d_in, const int* in_sizes, int n_in,
                              void* d_out, int out_size)
{
    const float* pos   = (const float*)d_in[0];
    const float* Wsp   = (const float*)d_in[1];
    const float* root  = (const float*)d_in[2];
    const float* bias  = (const float*)d_in[3];
    const float* gamma = (const float*)d_in[4];
    const float* beta  = (const float*)d_in[5];
    const float* W1    = (const float*)d_in[6];
    const float* b1    = (const float*)d_in[7];
    const float* W2    = (const float*)d_in[8];
    const float* b2    = (const float*)d_in[9];
    float* out = (float*)d_out;

    size_t smem = (size_t)PP*16 + 16*128*8;   // 64KB pos + 16KB Wsp = 80KB
    cudaFuncSetAttribute(k_point, cudaFuncAttributeMaxDynamicSharedMemorySize, (int)smem);

    k_point<<<BB*32, 128, smem>>>(pos, Wsp, root, bias);
    k_stats<<<FF, 256>>>();
    k_ys<<<R24*FF, 128>>>(gamma, beta);
    k_head<<<1, 256>>>(W1, b1, W2, b2, out);
}

// round 5
// speedup vs baseline: 1.9088x; 1.9088x over previous
#include <cuda_runtime.h>
#include <math.h>

#define BB   8
#define PP   4096
#define NN   (BB*PP)
#define KK   20
#define LL   10
#define FF   32
#define KSS  5
#define NCLS 40
#define R24  24
#define HALF 2048

// -------- persistent scratch --------
__device__ float g_kd[2*KK*NN];     // [slot(40)][n] distances
__device__ int   g_ki[2*KK*NN];     // [slot(40)][n] in-batch neighbor index
__device__ float g_node[NN*FF];
__device__ float g_v3[NN*3];
__device__ float g_stats[2*FF];
__device__ float g_ys[R24*FF];

// ---------------- power iteration (matches jax exactly) ----------------
__device__ __forceinline__ void power_iter(
    float m00, float m01, float m02, float m11, float m12, float m22,
    float &vx, float &vy, float &vz, float &lam)
{
    float x = 0.57735026918962576f, y = x, z = x;
    #pragma unroll
    for (int it = 0; it < 5; ++it) {
        float wx = m00*x + m01*y + m02*z;
        float wy = m01*x + m11*y + m12*z;
        float wz = m02*x + m12*y + m22*z;
        float nr = sqrtf(wx*wx + wy*wy + wz*wz);
        float inv = 1.0f / (nr + 1e-12f);
        x = wx*inv; y = wy*inv; z = wz*inv;
    }
    float wx = m00*x + m01*y + m02*z;
    float wy = m01*x + m11*y + m12*z;
    float wz = m02*x + m12*y + m22*z;
    lam = x*wx + y*wy + z*wz;
    vx = x; vy = y; vz = z;
}

// ---------------- kernel 1: half-range brute-force top-20 ----------------
// grid: 8 batches x 32 chunks x 2 halves = 512 blocks, 128 threads
__global__ void __launch_bounds__(128) k_knn(const float* __restrict__ pos)
{
    __shared__ float sx[HALF], sy[HALF], sz[HALF];
    int bx    = blockIdx.x;
    int b     = bx >> 6;
    int half  = (bx >> 5) & 1;
    int chunk = bx & 31;
    int tid   = threadIdx.x;

    const float* pb = pos + (size_t)b*PP*3;
    for (int i = tid; i < HALF; i += 128) {
        int j = half*HALF + i;
        sx[i] = pb[j*3+0]; sy[i] = pb[j*3+1]; sz[i] = pb[j*3+2];
    }
    __syncthreads();

    int sg = chunk*128 + tid;                 // self, in-batch
    float qx = pb[sg*3+0], qy = pb[sg*3+1], qz = pb[sg*3+2];
    int selfLocal = sg - half*HALF;
    if (selfLocal < 0 || selfLocal >= HALF) selfLocal = -1;

    float dist[KK]; int idx[KK];
    #pragma unroll
    for (int s = 0; s < KK; ++s) { dist[s] = 3.4e38f; idx[s] = 0; }

    #pragma unroll 1
    for (int jg = 0; jg < HALF; jg += 8) {
        float dd[8];
        #pragma unroll
        for (int u = 0; u < 8; ++u) {
            float dx = sx[jg+u] - qx, dy = sy[jg+u] - qy, dz = sz[jg+u] - qz;
            dd[u] = fmaf(dz, dz, fmaf(dy, dy, dx*dx));
        }
        float m = fminf(fminf(fminf(dd[0],dd[1]),fminf(dd[2],dd[3])),
                        fminf(fminf(dd[4],dd[5]),fminf(dd[6],dd[7])));

        // batched insert: each lane repeatedly extracts its own group-min.
        while (__any_sync(0xFFFFFFFFu, m < dist[KK-1])) {
            if (m < dist[KK-1]) {
                // lowest u with dd[u] == m  (preserves j-ascending tie order)
                int su = 7;
                if (dd[6] == m) su = 6;
                if (dd[5] == m) su = 5;
                if (dd[4] == m) su = 4;
                if (dd[3] == m) su = 3;
                if (dd[2] == m) su = 2;
                if (dd[1] == m) su = 1;
                if (dd[0] == m) su = 0;
                int jl = jg + su;
                #pragma unroll
                for (int u = 0; u < 8; ++u)
                    if (u == su) dd[u] = 3.4e38f;   // consume

                if (jl != selfLocal) {
                    float d = m;
                    int r = 0;
                    #pragma unroll
                    for (int s = 0; s < KK-1; ++s) r += (dist[s] <= d);
                    #pragma unroll
                    for (int s = KK-1; s >= 0; --s) {
                        bool sh = (s > r);
                        bool eq = (s == r);
                        float pd = (s > 0) ? dist[s-1] : d;
                        int   pi = (s > 0) ? idx[s-1]  : jl;
                        dist[s] = eq ? d  : (sh ? pd : dist[s]);
                        idx[s]  = eq ? jl : (sh ? pi : idx[s]);
                    }
                }
                m = fminf(fminf(fminf(dd[0],dd[1]),fminf(dd[2],dd[3])),
                          fminf(fminf(dd[4],dd[5]),fminf(dd[6],dd[7])));
            }
        }
    }

    int n = b*PP + sg;
    int base = half*KK;
    #pragma unroll
    for (int s = 0; s < KK; ++s) {
        g_kd[(size_t)(base+s)*NN + n] = dist[s];
        g_ki[(size_t)(base+s)*NN + n] = half*HALF + idx[s];
    }
}

// ---------------- kernel 2: merge halves + eig + spline conv ----------------
// grid: 256 (8 x 32 chunks), 128 threads
// smem: float4 pos[4096] (64K) + Wsp float2[16][128] (16K) + snb[128][21] (10.5K)
__global__ void __launch_bounds__(128, 2) k_feat(
    const float* __restrict__ pos,
    const float* __restrict__ Wsp,
    const float* __restrict__ root,
    const float* __restrict__ bias)
{
    extern __shared__ float smraw[];
    float4* sp  = (float4*)smraw;                       // 4096
    float2* sw  = (float2*)(smraw + 4*PP);              // 16*128
    int*    snb = (int*)   (smraw + 4*PP + 2*16*128);   // 128*21

    int b     = blockIdx.x >> 5;
    int chunk = blockIdx.x & 31;
    int tid   = threadIdx.x;

    for (int i = tid; i < PP; i += 128) {
        const float* p = pos + (size_t)(b*PP + i)*3;
        sp[i] = make_float4(p[0], p[1], p[2], 0.f);
    }
    for (int i = tid; i < 16*125; i += 128) {
        int f2 = i / 125, r = i - f2*125;
        sw[f2*128 + r] = make_float2(Wsp[r*32 + 2*f2], Wsp[r*32 + 2*f2 + 1]);
    }
    __syncthreads();

    int sg = chunk*128 + tid;
    int n  = b*PP + sg;
    float qx = sp[sg].x, qy = sp[sg].y, qz = sp[sg].z;

    // ---- merge the two sorted top-20 halves by rank ----
    {
        float dA[KK]; int jA[KK]; int cnt[KK];
        #pragma unroll
        for (int s = 0; s < KK; ++s) {
            dA[s] = g_kd[(size_t)s*NN + n];
            jA[s] = g_ki[(size_t)s*NN + n];
            cnt[s] = 0;
        }
        #pragma unroll 1
        for (int t = 0; t < KK; ++t) {
            float db = g_kd[(size_t)(KK+t)*NN + n];
            int   jb = g_ki[(size_t)(KK+t)*NN + n];
            int rb = t;
            #pragma unroll
            for (int s = 0; s < KK; ++s) {
                bool bltA = (db < dA[s]) || (db == dA[s] && jb < jA[s]);
                cnt[s] += bltA;
                rb     += !bltA;
            }
            if (rb < KK) snb[tid*21 + rb] = jb;
        }
        #pragma unroll
        for (int s = 0; s < KK; ++s) {
            int ra = s + cnt[s];
            if (ra < KK) snb[tid*21 + ra] = jA[s];
        }
    }

    int nb[KK];
    #pragma unroll
    for (int s = 0; s < KK; ++s) nb[s] = snb[tid*21 + s];

    // ---- covariance over the 10 nearest ----
    float cxx=0,cxy=0,cxz=0,cyy=0,cyz=0,czz=0;
    #pragma unroll
    for (int l = 0; l < LL; ++l) {
        float4 c = sp[nb[l]];
        float dx = c.x - qx, dy = c.y - qy, dz = c.z - qz;
        cxx += dx*dx; cxy += dx*dy; cxz += dx*dz;
        cyy += dy*dy; cyz += dy*dz; czz += dz*dz;
    }

    // ---- eigenvectors ----
    float v1x,v1y,v1z,l1;
    power_iter(cxx,cxy,cxz,cyy,cyz,czz, v1x,v1y,v1z,l1);
    float m00 = cxx - l1*v1x*v1x, m01 = cxy - l1*v1x*v1y, m02 = cxz - l1*v1x*v1z;
    float m11 = cyy - l1*v1y*v1y, m12 = cyz - l1*v1y*v1z, m22 = czz - l1*v1z*v1z;
    float v2x,v2y,v2z,l2;
    power_iter(m00,m01,m02,m11,m12,m22, v2x,v2y,v2z,l2);
    float v3x = v1y*v2z - v1z*v2y;
    float v3y = v1z*v2x - v1x*v2z;
    float v3z = v1x*v2y - v1y*v2x;
    float n3  = sqrtf(v3x*v3x + v3y*v3y + v3z*v3z);
    float i3  = 1.0f / (n3 + 1e-12f);
    v3x *= i3; v3y *= i3; v3z *= i3;

    // ---- pass A: sign and max-abs ----
    float ssum = 0.f, mx12 = 0.f, mx3 = 0.f;
    #pragma unroll
    for (int k = 0; k < KK; ++k) {
        float4 c = sp[nb[k]];
        float dx = c.x - qx, dy = c.y - qy, dz = c.z - qz;
        float d1 = dx*v1x + dy*v1y + dz*v1z;
        float d2 = dx*v2x + dy*v2y + dz*v2z;
        float d3 = dx*v3x + dy*v3y + dz*v3z;
        ssum += d3;
        mx12 = fmaxf(mx12, fmaxf(fabsf(d1), fabsf(d2)));
        mx3  = fmaxf(mx3, fabsf(d3));
    }
    float sgn    = (ssum > 0.f) ? 1.f : ((ssum < 0.f) ? -1.f : 0.f);
    float maxabs = (sgn != 0.f) ? fmaxf(mx12, mx3) : mx12;
    float rm     = 1.0f / maxabs;

    // ---- pass B: spline conv ----
    float msg[FF];
    #pragma unroll
    for (int f = 0; f < FF; ++f) msg[f] = 0.f;

    #pragma unroll 1
    for (int k = 0; k < KK; ++k) {
        float4 c = sp[nb[k]];
        float dx = c.x - qx, dy = c.y - qy, dz = c.z - qz;
        float d0 = dx*v1x + dy*v1y + dz*v1z;
        float d1 = dx*v2x + dy*v2y + dz*v2z;
        float d2 = (dx*v3x + dy*v3y + dz*v3z) * sgn;

        float vv0 = (d0*rm*0.5f + 0.5f)*4.f;
        float vv1 = (d1*rm*0.5f + 0.5f)*4.f;
        float vv2 = (d2*rm*0.5f + 0.5f)*4.f;
        float fl0 = floorf(vv0), fl1 = floorf(vv1), fl2 = floorf(vv2);
        float fr0 = vv0-fl0, fr1 = vv1-fl1, fr2 = vv2-fl2;
        int i0 = (int)fl0, i1 = (int)fl1, i2 = (int)fl2;

        int ia0 = min(max(i0,  0),4), ib0 = min(max(i0+1,0),4);
        int ia1 = min(max(i1,  0),4), ib1 = min(max(i1+1,0),4);
        int ia2 = min(max(i2,  0),4), ib2 = min(max(i2+1,0),4);
        float wa0 = 1.f-fr0, wb0 = fr0;
        float wa1 = 1.f-fr1, wb1 = fr1;
        float wa2 = 1.f-fr2, wb2 = fr2;

        #pragma unroll
        for (int s8 = 0; s8 < 8; ++s8) {
            int bit0 = (s8>>2)&1, bit1 = (s8>>1)&1, bit2 = s8&1;
            float bas = (bit0?wb0:wa0) * (bit1?wb1:wa1) * (bit2?wb2:wa2);
            int j0 = bit0?ib0:ia0, j1 = bit1?ib1:ia1, j2 = bit2?ib2:ia2;
            int flat = (j0*KSS + j1)*KSS + j2;
            #pragma unroll
            for (int f2 = 0; f2 < 16; ++f2) {
                float2 w = sw[f2*128 + flat];
                msg[2*f2]   += bas * w.x;
                msg[2*f2+1] += bas * w.y;
            }
        }
    }

    #pragma unroll
    for (int f = 0; f < FF; ++f)
        g_node[(size_t)n*FF + f] = msg[f] * (1.0f/(float)KK) + root[f] + bias[f];
    g_v3[n*3+0] = v3x; g_v3[n*3+1] = v3y; g_v3[n*3+2] = v3z;
}

// ---------------- kernel 3: per-channel batch stats ----------------
__global__ void k_stats()
{
    int c = blockIdx.x;
    int tid = threadIdx.x;
    double s = 0.0, s2 = 0.0;
    for (int i = tid; i < NN; i += 256) {
        float x = g_node[(size_t)i*FF + c];
        s  += (double)x;
        s2 += (double)x * (double)x;
    }
    __shared__ double rs[256], rs2[256];
    rs[tid] = s; rs2[tid] = s2;
    __syncthreads();
    for (int off = 128; off; off >>= 1) {
        if (tid < off) { rs[tid] += rs[tid+off]; rs2[tid] += rs2[tid+off]; }
        __syncthreads();
    }
    if (tid == 0) {
        double mu  = rs[0] / (double)NN;
        double var = rs2[0] / (double)NN - mu*mu;
        g_stats[c]      = (float)mu;
        g_stats[FF + c] = (float)(1.0 / sqrt(var + 1e-5));
    }
}

// ---------------- kernel 4: sigmoid + reshape(-1,P,F).mean(1) ----------------
__global__ void k_ys(const float* __restrict__ gamma, const float* __restrict__ beta)
{
    int r = blockIdx.x >> 5;
    int j = blockIdx.x & 31;
    int tid = threadIdx.x;
    float sum = 0.f;
    for (int p = tid; p < PP; p += 128) {
        int flat = r*(PP*FF) + p*FF + j;
        int nn   = flat / 96;
        int rem  = flat - nn*96;
        int fch  = rem / 3;
        int c    = rem - fch*3;
        float x  = g_node[(size_t)nn*FF + fch];
        float xb = gamma[fch] * (x - g_stats[fch]) * g_stats[FF + fch] + beta[fch];
        float o  = xb * g_v3[nn*3 + c];
        sum += 1.0f / (1.0f + expf(-o));
    }
    __shared__ float red[128];
    red[tid] = sum;
    __syncthreads();
    for (int off = 64; off; off >>= 1) {
        if (tid < off) red[tid] += red[tid+off];
        __syncthreads();
    }
    if (tid == 0) g_ys[r*FF + j] = red[0] / (float)PP;
}

// ---------------- kernel 5: MLP head + log_softmax (one block per row) --------
__global__ void k_head(
    const float* __restrict__ W1, const float* __restrict__ b1,
    const float* __restrict__ W2, const float* __restrict__ b2,
    float* __restrict__ out)
{
    __shared__ float ys[FF];
    __shared__ float y1[256];
    __shared__ float part[8][NCLS];
    __shared__ float zz[NCLS];
    __shared__ float s_lse;
    int r = blockIdx.x, tid = threadIdx.x;   // 320 threads

    if (tid < FF) ys[tid] = g_ys[r*FF + tid];
    __syncthreads();

    if (tid < 256) {
        float acc = b1[tid];
        #pragma unroll
        for (int f = 0; f < FF; ++f) acc = fmaf(ys[f], W1[f*256 + tid], acc);
        y1[tid] = acc > 0.f ? acc : expm1f(acc);
    }
    __syncthreads();

    {
        int c  = tid % NCLS;
        int sgm = tid / NCLS;     // 0..7
        float acc = 0.f;
        #pragma unroll
        for (int h = 0; h < 32; ++h) acc = fmaf(y1[sgm*32 + h], W2[(sgm*32+h)*NCLS + c], acc);
        part[sgm][c] = acc;
    }
    __syncthreads();

    if (tid < NCLS) {
        float acc = b2[tid];
        #pragma unroll
        for (int s = 0; s < 8; ++s) acc += part[s][tid];
        zz[tid] = acc;
    }
    __syncthreads();

    if (tid == 0) {
        float mx = -3.4e38f;
        for (int c = 0; c < NCLS; ++c) mx = fmaxf(mx, zz[c]);
        float se = 0.f;
        for (int c = 0; c < NCLS; ++c) se += expf(zz[c] - mx);
        s_lse = mx + logf(se);
    }
    __syncthreads();
    if (tid < NCLS) out[r*NCLS + tid] = zz[tid] - s_lse;
}

// ---------------- launch ----------------
extern "C" void kernel_launch(void* const* d_in, const int* in_sizes, int n_in,
                              void* d_out, int out_size)
{
    const float* pos   = (const float*)d_in[0];
    const float* Wsp   = (const float*)d_in[1];
    const float* root  = (const float*)d_in[2];
    const float* bias  = (const float*)d_in[3];
    const float* gamma = (const float*)d_in[4];
    const float* beta  = (const float*)d_in[5];
    const float* W1    = (const float*)d_in[6];
    const float* b1    = (const float*)d_in[7];
    const float* W2    = (const float*)d_in[8];
    const float* b2    = (const float*)d_in[9];
    float* out = (float*)d_out;

    size_t smem_feat = (size_t)PP*16 + 16*128*8 + 128*21*4;  // 64K + 16K + 10.5K
    cudaFuncSetAttribute(k_feat, cudaFuncAttributeMaxDynamicSharedMemorySize, (int)smem_feat);

    k_knn  <<<BB*32*2, 128>>>(pos);
    k_feat <<<BB*32, 128, smem_feat>>>(pos, Wsp, root, bias);
    k_stats<<<FF, 256>>>();
    k_ys   <<<R24*FF, 128>>>(gamma, beta);
    k_head <<<R24, 320>>>(W1, b1, W2, b2, out);
}

// round 7
// speedup vs baseline: 2.0567x; 1.0775x over previous
#include <cuda_runtime.h>
#include <math.h>

#define BB   8
#define PP   4096
#define NN   (BB*PP)
#define KK   20
#define LL   10
#define FF   32
#define KSS  5
#define NCLS 40
#define R24  24
#define QTR  1024

// -------- persistent scratch --------
__device__ unsigned long long g_ku[4*KK*NN];  // packed (dist_bits<<32 | idx), [slot(80)][n]
__device__ float  g_node[NN*FF];
__device__ float  g_v3[NN*3];
__device__ double g_acc[2*FF];      // [0..31] sum, [32..63] sumsq
__device__ float  g_stats[2*FF];    // [0..31] a = gamma*istd, [32..63] b = beta - mu*a
__device__ float  g_ys[R24*FF];

// ---------------- power iteration (matches jax exactly) ----------------
__device__ __forceinline__ void power_iter(
    float m00, float m01, float m02, float m11, float m12, float m22,
    float &vx, float &vy, float &vz, float &lam)
{
    float x = 0.57735026918962576f, y = x, z = x;
    #pragma unroll
    for (int it = 0; it < 5; ++it) {
        float wx = m00*x + m01*y + m02*z;
        float wy = m01*x + m11*y + m12*z;
        float wz = m02*x + m12*y + m22*z;
        float nr = sqrtf(wx*wx + wy*wy + wz*wz);
        float inv = 1.0f / (nr + 1e-12f);
        x = wx*inv; y = wy*inv; z = wz*inv;
    }
    float wx = m00*x + m01*y + m02*z;
    float wy = m01*x + m11*y + m12*z;
    float wz = m02*x + m12*y + m22*z;
    lam = x*wx + y*wy + z*wz;
    vx = x; vy = y; vz = z;
}

// ---------------- kernel 1: quarter-range brute-force top-20 ----------------
// grid: 8 batches x 32 chunks x 4 quarters = 1024 blocks, 128 threads
__global__ void __launch_bounds__(128) k_knn(const float* __restrict__ pos)
{
    __shared__ float4 sq[QTR];
    int bx    = blockIdx.x;
    int b     = bx >> 7;
    int qtr   = (bx >> 5) & 3;
    int chunk = bx & 31;
    int tid   = threadIdx.x;

    if (bx == 0 && tid < 64) g_acc[tid] = 0.0;   // zero stats accumulators

    const float* pb = pos + (size_t)b*PP*3;
    for (int i = tid; i < QTR; i += 128) {
        int j = qtr*QTR + i;
        sq[i] = make_float4(pb[j*3+0], pb[j*3+1], pb[j*3+2], 0.f);
    }
    __syncthreads();

    int sg = chunk*128 + tid;                 // self, in-batch
    float qx = pb[sg*3+0], qy = pb[sg*3+1], qz = pb[sg*3+2];
    int selfLocal = sg - qtr*QTR;
    if (selfLocal < 0 || selfLocal >= QTR) selfLocal = -1;

    float dist[KK]; int idx[KK];
    #pragma unroll
    for (int s = 0; s < KK; ++s) { dist[s] = 3.4e38f; idx[s] = 0; }

    #pragma unroll 1
    for (int jg = 0; jg < QTR; jg += 8) {
        float dd[8];
        #pragma unroll
        for (int u = 0; u < 8; ++u) {
            float4 c = sq[jg+u];                       // warp-uniform -> broadcast LDS.128
            float dx = c.x - qx, dy = c.y - qy, dz = c.z - qz;
            dd[u] = fmaf(dz, dz, fmaf(dy, dy, dx*dx));
        }
        float m = fminf(fminf(fminf(dd[0],dd[1]),fminf(dd[2],dd[3])),
                        fminf(fminf(dd[4],dd[5]),fminf(dd[6],dd[7])));

        while (__any_sync(0xFFFFFFFFu, m < dist[KK-1])) {
            if (m < dist[KK-1]) {
                int su = 7;
                if (dd[6] == m) su = 6;
                if (dd[5] == m) su = 5;
                if (dd[4] == m) su = 4;
                if (dd[3] == m) su = 3;
                if (dd[2] == m) su = 2;
                if (dd[1] == m) su = 1;
                if (dd[0] == m) su = 0;
                int jl = jg + su;
                #pragma unroll
                for (int u = 0; u < 8; ++u)
                    if (u == su) dd[u] = 3.4e38f;

                if (jl != selfLocal) {
                    float d = m;
                    int r = 0;
                    #pragma unroll
                    for (int s = 0; s < KK-1; ++s) r += (dist[s] <= d);
                    #pragma unroll
                    for (int s = KK-1; s >= 0; --s) {
                        bool sh = (s > r);
                        bool eq = (s == r);
                        float pd = (s > 0) ? dist[s-1] : d;
                        int   pi = (s > 0) ? idx[s-1]  : jl;
                        dist[s] = eq ? d  : (sh ? pd : dist[s]);
                        idx[s]  = eq ? jl : (sh ? pi : idx[s]);
                    }
                }
                m = fminf(fminf(fminf(dd[0],dd[1]),fminf(dd[2],dd[3])),
                          fminf(fminf(dd[4],dd[5]),fminf(dd[6],dd[7])));
            }
        }
    }

    int n = b*PP + sg;
    int base = qtr*KK;
    #pragma unroll
    for (int s = 0; s < KK; ++s) {
        unsigned long long pk =
            ((unsigned long long)__float_as_uint(dist[s]) << 32) |
            (unsigned int)(qtr*QTR + idx[s]);
        g_ku[(size_t)(base+s)*NN + n] = pk;
    }
}

// ---------------- kernel 2: merge quarters + eig + dense-basis spline conv ----
// grid: 256 (8 x 32 chunks), 128 threads
// smem: sx/sy/sz[4096] (48K) + merge rows / basis scratch (41984B) + W float4 (16000B)
__global__ void __launch_bounds__(128, 2) k_feat(
    const float* __restrict__ pos,
    const float* __restrict__ Wsp,
    const float* __restrict__ root,
    const float* __restrict__ bias)
{
    extern __shared__ char smch[];
    float* sx = (float*)smch;                 // 4096
    float* sy = sx + PP;
    float* sz = sy + PP;
    unsigned long long* mrg = (unsigned long long*)(smch + 49152);  // 128*41 u64
    float4* swW = (float4*)(smch + 49152 + 41984);                  // 1000 float4

    int b     = blockIdx.x >> 5;
    int chunk = blockIdx.x & 31;
    int tid   = threadIdx.x;
    int lane  = tid & 31;
    int wid   = tid >> 5;

    for (int i = tid; i < PP; i += 128) {
        const float* p = pos + (size_t)(b*PP + i)*3;
        sx[i] = p[0]; sy[i] = p[1]; sz[i] = p[2];
    }
    const float4* Wsp4 = (const float4*)Wsp;
    for (int i = tid; i < 125*8; i += 128) swW[i] = Wsp4[i];
    __syncthreads();

    int sg = chunk*128 + tid;
    int n  = b*PP + sg;
    float qx = sx[sg], qy = sy[sg], qz = sz[sg];

    // ---- 3-stage rank-merge of 4 sorted packed lists ----
    unsigned long long* rowA = mrg + tid*41;
    unsigned long long* rowB = rowA + 20;
    int nb[KK];
    {
        unsigned long long A[KK]; int cnt[KK];
        // stage 1: L0 (regs) with L1 (streamed from global) -> rowA
        #pragma unroll
        for (int s = 0; s < KK; ++s) { A[s] = g_ku[(size_t)s*NN + n]; cnt[s] = 0; }
        #pragma unroll 1
        for (int t = 0; t < KK; ++t) {
            unsigned long long ub = g_ku[(size_t)(KK+t)*NN + n];
            int rb = t;
            #pragma unroll
            for (int s = 0; s < KK; ++s) { bool blt = ub < A[s]; cnt[s] += blt; rb += !blt; }
            if (rb < KK) rowA[rb] = ub;
        }
        #pragma unroll
        for (int s = 0; s < KK; ++s) { int ra = s + cnt[s]; if (ra < KK) rowA[ra] = A[s]; }

        unsigned long long M1[KK];
        #pragma unroll
        for (int s = 0; s < KK; ++s) M1[s] = rowA[s];

        // stage 2: L2 (regs) with L3 (streamed) -> rowB
        #pragma unroll
        for (int s = 0; s < KK; ++s) { A[s] = g_ku[(size_t)(2*KK+s)*NN + n]; cnt[s] = 0; }
        #pragma unroll 1
        for (int t = 0; t < KK; ++t) {
            unsigned long long ub = g_ku[(size_t)(3*KK+t)*NN + n];
            int rb = t;
            #pragma unroll
            for (int s = 0; s < KK; ++s) { bool blt = ub < A[s]; cnt[s] += blt; rb += !blt; }
            if (rb < KK) rowB[rb] = ub;
        }
        #pragma unroll
        for (int s = 0; s < KK; ++s) { int ra = s + cnt[s]; if (ra < KK) rowB[ra] = A[s]; }

        // stage 3: M1 (regs) with rowB (streamed) -> rowA
        #pragma unroll
        for (int s = 0; s < KK; ++s) cnt[s] = 0;
        #pragma unroll 1
        for (int t = 0; t < KK; ++t) {
            unsigned long long ub = rowB[t];
            int rb = t;
            #pragma unroll
            for (int s = 0; s < KK; ++s) { bool blt = ub < M1[s]; cnt[s] += blt; rb += !blt; }
            if (rb < KK) rowA[rb] = ub;
        }
        #pragma unroll
        for (int s = 0; s < KK; ++s) { int ra = s + cnt[s]; if (ra < KK) rowA[ra] = M1[s]; }

        #pragma unroll
        for (int s = 0; s < KK; ++s) nb[s] = (int)(rowA[s] & 0xFFFFFFFFu);
    }

    // CRITICAL: mrg region is re-used as per-thread basis scratch below with a
    // DIFFERENT per-thread byte mapping (tid*252 vs tid*328). Without this
    // barrier a fast warp's sbas zeroing clobbers a slow warp's merge rows
    // while it is still reading them -> garbage nb -> OOB smem access.
    __syncthreads();

    // ---- covariance over the 10 nearest ----
    float cxx=0,cxy=0,cxz=0,cyy=0,cyz=0,czz=0;
    #pragma unroll
    for (int l = 0; l < LL; ++l) {
        int j = nb[l];
        float dx = sx[j]-qx, dy = sy[j]-qy, dz = sz[j]-qz;
        cxx += dx*dx; cxy += dx*dy; cxz += dx*dz;
        cyy += dy*dy; cyz += dy*dz; czz += dz*dz;
    }

    // ---- eigenvectors ----
    float v1x,v1y,v1z,l1;
    power_iter(cxx,cxy,cxz,cyy,cyz,czz, v1x,v1y,v1z,l1);
    float m00 = cxx - l1*v1x*v1x, m01 = cxy - l1*v1x*v1y, m02 = cxz - l1*v1x*v1z;
    float m11 = cyy - l1*v1y*v1y, m12 = cyz - l1*v1y*v1z, m22 = czz - l1*v1z*v1z;
    float v2x,v2y,v2z,l2;
    power_iter(m00,m01,m02,m11,m12,m22, v2x,v2y,v2z,l2);
    float v3x = v1y*v2z - v1z*v2y;
    float v3y = v1z*v2x - v1x*v2z;
    float v3z = v1x*v2y - v1y*v2x;
    float n3  = sqrtf(v3x*v3x + v3y*v3y + v3z*v3z);
    float i3  = 1.0f / (n3 + 1e-12f);
    v3x *= i3; v3y *= i3; v3z *= i3;

    // ---- pass A: sign and max-abs ----
    float ssum = 0.f, mx12 = 0.f, mx3 = 0.f;
    #pragma unroll
    for (int k = 0; k < KK; ++k) {
        int j = nb[k];
        float dx = sx[j]-qx, dy = sy[j]-qy, dz = sz[j]-qz;
        float d1 = dx*v1x + dy*v1y + dz*v1z;
        float d2 = dx*v2x + dy*v2y + dz*v2z;
        float d3 = dx*v3x + dy*v3y + dz*v3z;
        ssum += d3;
        mx12 = fmaxf(mx12, fmaxf(fabsf(d1), fabsf(d2)));
        mx3  = fmaxf(mx3, fabsf(d3));
    }
    float sgn    = (ssum > 0.f) ? 1.f : ((ssum < 0.f) ? -1.f : 0.f);
    float maxabs = (sgn != 0.f) ? fmaxf(mx12, mx3) : mx12;
    float rm     = 1.0f / maxabs;

    // ---- pass B: dense-basis spline conv in 2 cell-range passes ----
    float msg[FF];
    #pragma unroll
    for (int f = 0; f < FF; ++f) msg[f] = 0.f;

    float* sbas = (float*)mrg;        // reuse merge scratch: stride-63 per-thread rows
    int off = tid*63;

    #pragma unroll 1
    for (int pass = 0; pass < 2; ++pass) {
        int lo    = pass ? 63 : 0;
        int width = pass ? 62 : 63;

        for (int c = 0; c < 63; ++c) sbas[off + c] = 0.f;

        #pragma unroll 1
        for (int k = 0; k < KK; ++k) {
            int j = nb[k];
            float dx = sx[j]-qx, dy = sy[j]-qy, dz = sz[j]-qz;
            float d0 = dx*v1x + dy*v1y + dz*v1z;
            float d1 = dx*v2x + dy*v2y + dz*v2z;
            float d2 = (dx*v3x + dy*v3y + dz*v3z) * sgn;

            float vv0 = (d0*rm*0.5f + 0.5f)*4.f;
            float vv1 = (d1*rm*0.5f + 0.5f)*4.f;
            float vv2 = (d2*rm*0.5f + 0.5f)*4.f;
            float fl0 = floorf(vv0), fl1 = floorf(vv1), fl2 = floorf(vv2);
            float fr0 = vv0-fl0, fr1 = vv1-fl1, fr2 = vv2-fl2;
            int i0 = (int)fl0, i1 = (int)fl1, i2 = (int)fl2;

            int ia0 = min(max(i0,  0),4), ib0 = min(max(i0+1,0),4);
            int ia1 = min(max(i1,  0),4), ib1 = min(max(i1+1,0),4);
            int ia2 = min(max(i2,  0),4), ib2 = min(max(i2+1,0),4);
            float wa0 = 1.f-fr0, wb0 = fr0;
            float wa1 = 1.f-fr1, wb1 = fr1;
            float wa2 = 1.f-fr2, wb2 = fr2;

            #pragma unroll
            for (int s8 = 0; s8 < 8; ++s8) {
                int bit0 = (s8>>2)&1, bit1 = (s8>>1)&1, bit2 = s8&1;
                float bas = (bit0?wb0:wa0) * (bit1?wb1:wa1) * (bit2?wb2:wa2);
                int j0 = bit0?ib0:ia0, j1 = bit1?ib1:ia1, j2 = bit2?ib2:ia2;
                int cell = (j0*KSS + j1)*KSS + j2;
                int loc  = cell - lo;
                if (loc >= 0 && loc < width)
                    sbas[off + loc] += bas;
            }
        }

        // dense GEMV: W cell index is warp-uniform -> broadcast LDS.128
        #pragma unroll 4
        for (int c = 0; c < width; ++c) {
            float bb = sbas[off + c];
            int cell = lo + c;
            #pragma unroll
            for (int f4 = 0; f4 < 8; ++f4) {
                float4 w = swW[cell*8 + f4];
                msg[4*f4+0] += bb * w.x;
                msg[4*f4+1] += bb * w.y;
                msg[4*f4+2] += bb * w.z;
                msg[4*f4+3] += bb * w.w;
            }
        }
    }

    // ---- node output + fused batch-stat accumulation ----
    float keepS = 0.f, keepS2 = 0.f;
    #pragma unroll
    for (int f = 0; f < FF; ++f) {
        float v = msg[f] * (1.0f/(float)KK) + root[f] + bias[f];
        g_node[(size_t)n*FF + f] = v;
        float s = v, s2 = v*v;
        #pragma unroll
        for (int o2 = 16; o2; o2 >>= 1) {
            s  += __shfl_xor_sync(0xFFFFFFFFu, s,  o2);
            s2 += __shfl_xor_sync(0xFFFFFFFFu, s2, o2);
        }
        if (lane == f) { keepS = s; keepS2 = s2; }
    }
    g_v3[n*3+0] = v3x; g_v3[n*3+1] = v3y; g_v3[n*3+2] = v3z;

    __shared__ float blkS[4][FF], blkS2[4][FF];
    blkS[wid][lane] = keepS; blkS2[wid][lane] = keepS2;
    __syncthreads();
    if (wid == 0) {
        float tS  = blkS[0][lane]  + blkS[1][lane]  + blkS[2][lane]  + blkS[3][lane];
        float tS2 = blkS2[0][lane] + blkS2[1][lane] + blkS2[2][lane] + blkS2[3][lane];
        atomicAdd(&g_acc[lane],      (double)tS);
        atomicAdd(&g_acc[FF + lane], (double)tS2);
    }
}

// ---------------- kernel 3: finalize stats, pre-fold BN into a*x+b -------------
__global__ void k_fin(const float* __restrict__ gamma, const float* __restrict__ beta)
{
    int f = threadIdx.x;  // 32
    double mu  = g_acc[f] / (double)NN;
    double var = g_acc[FF+f] / (double)NN - mu*mu;
    float istd = (float)(1.0 / sqrt(var + 1e-5));
    float a = gamma[f] * istd;
    float bb = beta[f] - (float)mu * a;
    g_stats[f]      = a;
    g_stats[FF + f] = bb;
}

// ---------------- kernel 4: sigmoid + reshape(-1,P,F).mean(1) ----------------
__global__ void k_ys()
{
    int r = blockIdx.x >> 5;
    int j = blockIdx.x & 31;
    int tid = threadIdx.x;
    float sum = 0.f;
    #pragma unroll 4
    for (int p = tid; p < PP; p += 128) {
        int flat = r*(PP*FF) + p*FF + j;
        int nn   = flat / 96;
        int rem  = flat - nn*96;
        int fch  = rem / 3;
        int c    = rem - fch*3;
        float x  = g_node[(size_t)nn*FF + fch];
        float xb = fmaf(g_stats[fch], x, g_stats[FF + fch]);
        float o  = xb * g_v3[nn*3 + c];
        sum += __fdividef(1.f, 1.f + __expf(-o));
    }
    __shared__ float red[128];
    red[tid] = sum;
    __syncthreads();
    for (int off = 64; off; off >>= 1) {
        if (tid < off) red[tid] += red[tid+off];
        __syncthreads();
    }
    if (tid == 0) g_ys[r*FF + j] = red[0] / (float)PP;
}

// ---------------- kernel 5: MLP head + log_softmax (one block per row) --------
__global__ void k_head(
    const float* __restrict__ W1, const float* __restrict__ b1,
    const float* __restrict__ W2, const float* __restrict__ b2,
    float* __restrict__ out)
{
    __shared__ float ys[FF];
    __shared__ float y1[256];
    __shared__ float part[8][NCLS];
    __shared__ float zz[NCLS];
    __shared__ float s_lse;
    int r = blockIdx.x, tid = threadIdx.x;   // 320 threads

    if (tid < FF) ys[tid] = g_ys[r*FF + tid];
    __syncthreads();

    if (tid < 256) {
        float acc = b1[tid];
        #pragma unroll
        for (int f = 0; f < FF; ++f) acc = fmaf(ys[f], W1[f*256 + tid], acc);
        y1[tid] = acc > 0.f ? acc : expm1f(acc);
    }
    __syncthreads();

    {
        int c  = tid % NCLS;
        int sgm = tid / NCLS;     // 0..7
        float acc = 0.f;
        #pragma unroll
        for (int h = 0; h < 32; ++h) acc = fmaf(y1[sgm*32 + h], W2[(sgm*32+h)*NCLS + c], acc);
        part[sgm][c] = acc;
    }
    __syncthreads();

    if (tid < NCLS) {
        float acc = b2[tid];
        #pragma unroll
        for (int s = 0; s < 8; ++s) acc += part[s][tid];
        zz[tid] = acc;
    }
    __syncthreads();

    if (tid == 0) {
        float mx = -3.4e38f;
        for (int c = 0; c < NCLS; ++c) mx = fmaxf(mx, zz[c]);
        float se = 0.f;
        for (int c = 0; c < NCLS; ++c) se += expf(zz[c] - mx);
        s_lse = mx + logf(se);
    }
    __syncthreads();
    if (tid < NCLS) out[r*NCLS + tid] = zz[tid] - s_lse;
}

// ---------------- launch ----------------
extern "C" void kernel_launch(void* const* d_in, const int* in_sizes, int n_in,
                              void* d_out, int out_size)
{
    const float* pos   = (const float*)d_in[0];
    const float* Wsp   = (const float*)d_in[1];
    const float* root  = (const float*)d_in[2];
    const float* bias  = (const float*)d_in[3];
    const float* gamma = (const float*)d_in[4];
    const float* beta  = (const float*)d_in[5];
    const float* W1    = (const float*)d_in[6];
    const float* b1    = (const float*)d_in[7];
    const float* W2    = (const float*)d_in[8];
    const float* b2    = (const float*)d_in[9];
    float* out = (float*)d_out;

    size_t smem_feat = 49152 + 41984 + 16000;   // 107,136 B
    cudaFuncSetAttribute(k_feat, cudaFuncAttributeMaxDynamicSharedMemorySize, (int)smem_feat);

    k_knn  <<<BB*32*4, 128>>>(pos);
    k_feat <<<BB*32, 128, smem_feat>>>(pos, Wsp, root, bias);
    k_fin  <<<1, 32>>>(gamma, beta);
    k_ys   <<<R24*FF, 128>>>();
    k_head <<<R24, 320>>>(W1, b1, W2, b2, out);
}